// round 1
// baseline (speedup 1.0000x reference)
#include <cuda_runtime.h>

#define NN 50000
#define EE 800000
#define FF 29
#define C0 32
#define HH 64
#define BB 50
#define LL 7

// ---------------- scratch (device globals; no allocations) ----------------
__device__ float g_h0[NN * C0];        // layer-0 input [N,32]
__device__ float g_hA[NN * HH];        // ping
__device__ float g_hB[NN * HH];        // pong
__device__ int   g_rowptr[NN + 1];     // CSR row pointers (by dst)
__device__ int   g_cursor[NN];         // counts, then scatter cursors
__device__ int   g_csr[EE];            // CSR column indices (src)
__device__ float g_pool[BB * HH];      // per-graph sums
__device__ int   g_cnt[BB];            // per-graph node counts

// ---------------- init / CSR build ----------------
__global__ void init_kernel() {
    int i = blockIdx.x * blockDim.x + threadIdx.x;
    if (i < NN) g_cursor[i] = 0;
    if (i < BB * HH) g_pool[i] = 0.f;
    if (i < BB) g_cnt[i] = 0;
}

__global__ void build_h0(const float* __restrict__ x, const float* __restrict__ pos) {
    int i = blockIdx.x * blockDim.x + threadIdx.x;
    if (i >= NN * C0) return;
    int v = i >> 5, c = i & 31;
    float val;
    if (c < FF) val = x[v * FF + c];
    else        val = pos[v * 3 + (c - FF)];
    g_h0[i] = val;
}

__global__ void hist_kernel(const int* __restrict__ dst) {
    int e = blockIdx.x * blockDim.x + threadIdx.x;
    if (e < EE) atomicAdd(&g_cursor[dst[e]], 1);
}

// single-block exclusive scan of g_cursor[0..NN) -> g_rowptr[0..NN]
__global__ void scan_kernel() {
    __shared__ int wsum[32];
    __shared__ int carry;
    if (threadIdx.x == 0) { carry = 0; g_rowptr[0] = 0; }
    __syncthreads();
    int lane = threadIdx.x & 31, wid = threadIdx.x >> 5;
    for (int base = 0; base < NN; base += 1024) {
        int i = base + threadIdx.x;
        int v = (i < NN) ? g_cursor[i] : 0;
        int xx = v;
        #pragma unroll
        for (int o = 1; o < 32; o <<= 1) {
            int y = __shfl_up_sync(0xffffffffu, xx, o);
            if (lane >= o) xx += y;
        }
        if (lane == 31) wsum[wid] = xx;
        __syncthreads();
        if (wid == 0) {
            int s = wsum[lane];
            #pragma unroll
            for (int o = 1; o < 32; o <<= 1) {
                int y = __shfl_up_sync(0xffffffffu, s, o);
                if (lane >= o) s += y;
            }
            wsum[lane] = s;
        }
        __syncthreads();
        int incl = xx + (wid ? wsum[wid - 1] : 0) + carry;
        if (i < NN) g_rowptr[i + 1] = incl;
        __syncthreads();
        if (threadIdx.x == 1023) carry = incl;
        __syncthreads();
    }
}

__global__ void copy_cursor() {
    int i = blockIdx.x * blockDim.x + threadIdx.x;
    if (i < NN) g_cursor[i] = g_rowptr[i];
}

__global__ void scatter_kernel(const int* __restrict__ src, const int* __restrict__ dst) {
    int e = blockIdx.x * blockDim.x + threadIdx.x;
    if (e >= EE) return;
    int p = atomicAdd(&g_cursor[dst[e]], 1);
    g_csr[p] = src[e];
}

// ---------------- fused GIN layer ----------------
// One warp handles 4 nodes. z distributed across lanes (feature c on lane c%32,
// half select by c/32). Weights in SMEM; z broadcast via SHFL.IDX, weight LDS
// amortized over the 4 nodes.
template <int C, bool RELU_OUT>
__global__ void __launch_bounds__(256) gin_layer(
    const float* __restrict__ h_in, float* __restrict__ h_out,
    const float* __restrict__ W1, const float* __restrict__ b1,
    const float* __restrict__ W2, const float* __restrict__ b2)
{
    __shared__ float sW1[C * HH];
    __shared__ float sW2[HH * HH];
    __shared__ float sb1[HH], sb2[HH];
    for (int i = threadIdx.x; i < C * HH; i += 256) sW1[i] = W1[i];
    for (int i = threadIdx.x; i < HH * HH; i += 256) sW2[i] = W2[i];
    if (threadIdx.x < HH) { sb1[threadIdx.x] = b1[threadIdx.x]; sb2[threadIdx.x] = b2[threadIdx.x]; }
    __syncthreads();

    const int lane  = threadIdx.x & 31;
    const int vbase = (blockIdx.x * 8 + (threadIdx.x >> 5)) * 4;

    // --- gather: z = h[v] + sum_{e: dst==v} h[src_e]
    float zlo[4] = {0.f, 0.f, 0.f, 0.f};
    float zhi[4] = {0.f, 0.f, 0.f, 0.f};
    #pragma unroll
    for (int n = 0; n < 4; n++) {
        int v = vbase + n;
        if (v >= NN) break;
        zlo[n] = __ldg(&h_in[v * C + lane]);
        if (C == 64) zhi[n] = __ldg(&h_in[v * C + 32 + lane]);
        int e1 = __ldg(&g_rowptr[v + 1]);
        for (int e = __ldg(&g_rowptr[v]); e < e1; e++) {
            int s = __ldg(&g_csr[e]);
            zlo[n] += __ldg(&h_in[s * C + lane]);
            if (C == 64) zhi[n] += __ldg(&h_in[s * C + 32 + lane]);
        }
    }

    // --- GEMV1: t = relu(z @ W1 + b1)
    float t0[4], t1[4];
    #pragma unroll
    for (int n = 0; n < 4; n++) { t0[n] = sb1[lane]; t1[n] = sb1[lane + 32]; }
    #pragma unroll 4
    for (int c = 0; c < 32; c++) {
        float w0 = sW1[c * HH + lane], w1 = sW1[c * HH + 32 + lane];
        #pragma unroll
        for (int n = 0; n < 4; n++) {
            float zc = __shfl_sync(0xffffffffu, zlo[n], c);
            t0[n] = fmaf(zc, w0, t0[n]);
            t1[n] = fmaf(zc, w1, t1[n]);
        }
    }
    if (C == 64) {
        #pragma unroll 4
        for (int c = 0; c < 32; c++) {
            float w0 = sW1[(c + 32) * HH + lane], w1 = sW1[(c + 32) * HH + 32 + lane];
            #pragma unroll
            for (int n = 0; n < 4; n++) {
                float zc = __shfl_sync(0xffffffffu, zhi[n], c);
                t0[n] = fmaf(zc, w0, t0[n]);
                t1[n] = fmaf(zc, w1, t1[n]);
            }
        }
    }
    #pragma unroll
    for (int n = 0; n < 4; n++) { t0[n] = fmaxf(t0[n], 0.f); t1[n] = fmaxf(t1[n], 0.f); }

    // --- GEMV2: o = t @ W2 + b2 (optional relu)
    float o0[4], o1[4];
    #pragma unroll
    for (int n = 0; n < 4; n++) { o0[n] = sb2[lane]; o1[n] = sb2[lane + 32]; }
    #pragma unroll 4
    for (int c = 0; c < 32; c++) {
        float w0 = sW2[c * HH + lane], w1 = sW2[c * HH + 32 + lane];
        #pragma unroll
        for (int n = 0; n < 4; n++) {
            float zc = __shfl_sync(0xffffffffu, t0[n], c);
            o0[n] = fmaf(zc, w0, o0[n]);
            o1[n] = fmaf(zc, w1, o1[n]);
        }
    }
    #pragma unroll 4
    for (int c = 0; c < 32; c++) {
        float w0 = sW2[(c + 32) * HH + lane], w1 = sW2[(c + 32) * HH + 32 + lane];
        #pragma unroll
        for (int n = 0; n < 4; n++) {
            float zc = __shfl_sync(0xffffffffu, t1[n], c);
            o0[n] = fmaf(zc, w0, o0[n]);
            o1[n] = fmaf(zc, w1, o1[n]);
        }
    }

    #pragma unroll
    for (int n = 0; n < 4; n++) {
        int v = vbase + n;
        if (v >= NN) break;
        float a = o0[n], b = o1[n];
        if (RELU_OUT) { a = fmaxf(a, 0.f); b = fmaxf(b, 0.f); }
        h_out[v * HH + lane]      = a;
        h_out[v * HH + 32 + lane] = b;
    }
}

// ---------------- pooling + final linear ----------------
__global__ void pool_kernel(const float* __restrict__ h, const int* __restrict__ batch) {
    int gtid = blockIdx.x * blockDim.x + threadIdx.x;
    int v = gtid >> 5, lane = threadIdx.x & 31;
    if (v >= NN) return;
    int g = __ldg(&batch[v]);
    float2 val = *(const float2*)&h[v * HH + 2 * lane];
    atomicAdd((float2*)&g_pool[g * HH + 2 * lane], val);
    if (lane == 0) atomicAdd(&g_cnt[g], 1);
}

__global__ void final_kernel(const float* __restrict__ lin_w,
                             const float* __restrict__ lin_b,
                             float* __restrict__ out) {
    int gtid = blockIdx.x * blockDim.x + threadIdx.x;
    int g = gtid >> 5, lane = threadIdx.x & 31;
    if (g >= BB) return;
    float s = g_pool[g * HH + lane] * __ldg(&lin_w[lane]) +
              g_pool[g * HH + 32 + lane] * __ldg(&lin_w[32 + lane]);
    #pragma unroll
    for (int o = 16; o; o >>= 1) s += __shfl_xor_sync(0xffffffffu, s, o);
    if (lane == 0) out[g] = s / fmaxf((float)g_cnt[g], 1.f) + lin_b[0];
}

// ---------------- launch ----------------
extern "C" void kernel_launch(void* const* d_in, const int* in_sizes, int n_in,
                              void* d_out, int out_size) {
    const float* x     = (const float*)d_in[0];
    const float* pos   = (const float*)d_in[1];
    const int*   ei    = (const int*)d_in[2];
    const int*   batch = (const int*)d_in[3];
    const float* W1f   = (const float*)d_in[4];
    const float* W1r   = (const float*)d_in[5];
    const float* b1    = (const float*)d_in[6];
    const float* W2    = (const float*)d_in[7];
    const float* b2    = (const float*)d_in[8];
    const float* lin_w = (const float*)d_in[9];
    const float* lin_b = (const float*)d_in[10];
    float* out = (float*)d_out;

    const int* src = ei;       // edge_index[0]
    const int* dst = ei + EE;  // edge_index[1]

    float *h0, *hA, *hB;
    cudaGetSymbolAddress((void**)&h0, g_h0);
    cudaGetSymbolAddress((void**)&hA, g_hA);
    cudaGetSymbolAddress((void**)&hB, g_hB);

    init_kernel<<<(NN + 255) / 256, 256>>>();
    build_h0<<<(NN * C0 + 255) / 256, 256>>>(x, pos);
    hist_kernel<<<(EE + 255) / 256, 256>>>(dst);
    scan_kernel<<<1, 1024>>>();
    copy_cursor<<<(NN + 255) / 256, 256>>>();
    scatter_kernel<<<(EE + 255) / 256, 256>>>(src, dst);

    const int nblk = (NN + 31) / 32;  // 32 nodes / block (8 warps x 4 nodes)

    // layer 0: C=32, trailing relu
    gin_layer<32, true><<<nblk, 256>>>(h0, hA, W1f, b1, W2, b2);

    float* cur = hA;
    float* nxt = hB;
    for (int l = 1; l < LL; l++) {
        const float* w1 = W1r + (size_t)(l - 1) * HH * HH;
        if (l < LL - 1)
            gin_layer<64, true><<<nblk, 256>>>(cur, nxt, w1, b1 + l * HH,
                                               W2 + (size_t)l * HH * HH, b2 + l * HH);
        else
            gin_layer<64, false><<<nblk, 256>>>(cur, nxt, w1, b1 + l * HH,
                                                W2 + (size_t)l * HH * HH, b2 + l * HH);
        float* t = cur; cur = nxt; nxt = t;
    }
    // final features now in `cur`

    pool_kernel<<<(NN * 32 + 255) / 256, 256>>>(cur, batch);
    final_kernel<<<(BB * 32 + 255) / 256, 256>>>(lin_w, lin_b, out);
}